// round 3
// baseline (speedup 1.0000x reference)
#include <cuda_runtime.h>

#define NN 2048
#define DIN 128
#define HH 256
#define DE 64
#define JSPLIT 4
#define BMR 32
#define BJ 32
#define EPAD 67   // odd pad -> conflict-free row access by lane
#define SPAD 33

__device__ float g_outx[NN * HH];
__device__ float g_emb[NN * DE];
__device__ float g_sq[NN];
__device__ float g_xl[NN * DIN];
__device__ float g_degp[JSPLIT * NN];
__device__ float g_accp[JSPLIT * NN * DIN];

__device__ __forceinline__ float fast_rcp(float x) {
    float r = __uint_as_float(0x7EF311C3u - __float_as_uint(x));
    r = r * (2.0f - x * r);
    r = r * (2.0f - x * r);
    return r;
}

// ---------------------------------------------------------------------------
// Generic tiled GEMM with bias + optional ReLU.  C[M,N] = act(A[M,K]@B[K,N]+b)
// BM=BN=64, BK=16, 256 threads, 4x4 per thread. All dims multiples of tile.
// ---------------------------------------------------------------------------
template <bool RELU>
__global__ void gemm_bias_kernel(const float* __restrict__ A,
                                 const float* __restrict__ B,
                                 const float* __restrict__ bias,
                                 float* __restrict__ C,
                                 int M, int N, int K) {
    __shared__ float As[16][64];
    __shared__ float Bs[16][65];
    int tid = threadIdx.x;
    int tx = tid & 15, ty = tid >> 4;
    int mbase = blockIdx.y * 64;
    int nbase = blockIdx.x * 64;

    float acc[4][4];
#pragma unroll
    for (int i = 0; i < 4; i++)
#pragma unroll
        for (int j = 0; j < 4; j++) acc[i][j] = 0.f;

    for (int k0 = 0; k0 < K; k0 += 16) {
        {
            int m = tid >> 2;
            int k = (tid & 3) << 2;
            float4 av = *reinterpret_cast<const float4*>(
                A + (size_t)(mbase + m) * K + k0 + k);
            As[k + 0][m] = av.x; As[k + 1][m] = av.y;
            As[k + 2][m] = av.z; As[k + 3][m] = av.w;
        }
#pragma unroll
        for (int r = 0; r < 4; r++) {
            int idx = tid + r * 256;
            int kk = idx >> 6, n = idx & 63;
            Bs[kk][n] = B[(size_t)(k0 + kk) * N + nbase + n];
        }
        __syncthreads();
#pragma unroll
        for (int kk = 0; kk < 16; kk++) {
            float a[4], b[4];
#pragma unroll
            for (int i = 0; i < 4; i++) a[i] = As[kk][ty * 4 + i];
#pragma unroll
            for (int j = 0; j < 4; j++) b[j] = Bs[kk][tx * 4 + j];
#pragma unroll
            for (int i = 0; i < 4; i++)
#pragma unroll
                for (int j = 0; j < 4; j++) acc[i][j] += a[i] * b[j];
        }
        __syncthreads();
    }
#pragma unroll
    for (int i = 0; i < 4; i++) {
        int row = mbase + ty * 4 + i;
#pragma unroll
        for (int j = 0; j < 4; j++) {
            int col = nbase + tx * 4 + j;
            float v = acc[i][j] + bias[col];
            if (RELU) v = v > 0.f ? v : 0.f;
            C[(size_t)row * N + col] = v;
        }
    }
}

// ---------------------------------------------------------------------------
// Row squared norms of emb [NN, 64]: one warp per row.
// ---------------------------------------------------------------------------
__global__ void sq_kernel(const float* __restrict__ emb, float* __restrict__ sq) {
    int row = blockIdx.x * 8 + (threadIdx.x >> 5);
    int lane = threadIdx.x & 31;
    float v0 = emb[row * DE + lane];
    float v1 = emb[row * DE + 32 + lane];
    float s = v0 * v0 + v1 * v1;
#pragma unroll
    for (int o = 16; o > 0; o >>= 1) s += __shfl_xor_sync(0xffffffffu, s, o);
    if (lane == 0) sq[row] = s;
}

// ---------------------------------------------------------------------------
// Fused adjacency kernel.
// Block = 32 rows of A x 512 columns (one j-split). 256 threads.
// Per j-tile (32 cols): compute S = sigmoid((1+t)*dist + (5+th)) + eye,
// write adj coalesced, accumulate deg and acc += S @ x_last in registers.
// ---------------------------------------------------------------------------
__global__ void adj_kernel(const float* __restrict__ emb,
                           const float* __restrict__ sq,
                           const float* __restrict__ xl,
                           const float* __restrict__ temp_p,
                           const float* __restrict__ theta_p,
                           float* __restrict__ adj_out,
                           float* __restrict__ degp,
                           float* __restrict__ accp) {
    __shared__ float embi[BMR * EPAD];
    __shared__ float embj[BJ * EPAD];
    __shared__ float xls[BJ * DIN];
    __shared__ float Ssm[BMR * SPAD];
    __shared__ float sqis[BMR];
    __shared__ float sqjs[BJ];
    __shared__ float degred[8][32];

    const int t = threadIdx.x;
    const int i0 = blockIdx.x * BMR;
    const int tiles = (NN / BJ) / JSPLIT;           // 16
    const int j0 = blockIdx.y * (tiles * BJ);
    const float cA = 1.0f + *temp_p;
    const float cB = 5.0f + *theta_p;

    // load emb rows for this i-block (reused across all j-tiles)
    for (int idx = t; idx < BMR * DE; idx += 256) {
        int r = idx >> 6, c = idx & 63;
        embi[r * EPAD + c] = emb[(size_t)(i0 + r) * DE + c];
    }
    if (t < BMR) sqis[t] = sq[i0 + t];

    const int i = t & 31;        // row within block
    const int wq = t >> 5;       // warp id 0..7 -> jj quad / d group
    float acc[16];
#pragma unroll
    for (int u = 0; u < 16; u++) acc[u] = 0.f;
    float degacc = 0.f;

    for (int jt = 0; jt < tiles; ++jt) {
        const int jb = j0 + jt * BJ;
        __syncthreads();  // protect smem reuse (also covers first-iter embi)

        for (int idx = t; idx < BJ * DE; idx += 256) {
            int r = idx >> 6, c = idx & 63;
            embj[r * EPAD + c] = emb[(size_t)(jb + r) * DE + c];
        }
        for (int idx = t; idx < BJ * DIN; idx += 256)
            xls[idx] = xl[(size_t)jb * DIN + idx];
        if (t < BJ) sqjs[t] = sq[jb + t];
        __syncthreads();

        // ---- S tile: thread computes rows i, cols jj = wq*4 + q ----
        float dot[4] = {0.f, 0.f, 0.f, 0.f};
        const float* ei = &embi[i * EPAD];
#pragma unroll 16
        for (int k = 0; k < DE; k++) {
            float a = ei[k];
#pragma unroll
            for (int q = 0; q < 4; q++)
                dot[q] += a * embj[(wq * 4 + q) * EPAD + k];
        }
#pragma unroll
        for (int q = 0; q < 4; q++) {
            int jj = wq * 4 + q;
            float z = cA * (2.f * dot[q] - sqis[i] - sqjs[jj]) + cB;
            float e = __expf(-z);
            float p = fast_rcp(1.f + e);
            if (i0 + i == jb + jj) p += 1.f;
            degacc += p;
            Ssm[i * SPAD + jj] = p;
        }
        __syncthreads();

        // ---- coalesced adjacency write (row-contiguous 128B segments) ----
        for (int idx = t; idx < BMR * BJ; idx += 256) {
            int r = idx >> 5, c = idx & 31;
            adj_out[(size_t)(i0 + r) * NN + jb + c] = Ssm[r * SPAD + c];
        }

        // ---- acc += S @ x_last  (thread: row i, d-cols wq*16..wq*16+15) ----
        const float4* xls4 = reinterpret_cast<const float4*>(xls);
#pragma unroll
        for (int jj = 0; jj < BJ; ++jj) {
            float s = Ssm[i * SPAD + jj];
#pragma unroll
            for (int v = 0; v < 4; ++v) {
                float4 xv = xls4[jj * 32 + wq * 4 + v];
                acc[v * 4 + 0] += s * xv.x;
                acc[v * 4 + 1] += s * xv.y;
                acc[v * 4 + 2] += s * xv.z;
                acc[v * 4 + 3] += s * xv.w;
            }
        }
    }

    // ---- deterministic deg reduction (fixed-order tree via smem) ----
    degred[wq][i] = degacc;
    __syncthreads();
    if (t < 32) {
        float d = 0.f;
#pragma unroll
        for (int w = 0; w < 8; w++) d += degred[w][t];
        degp[blockIdx.y * NN + i0 + t] = d;
    }

    // ---- write partial acc ----
    float* ap = &accp[((size_t)blockIdx.y * NN + i0 + i) * DIN + wq * 16];
#pragma unroll
    for (int u = 0; u < 16; u++) ap[u] = acc[u];
}

// ---------------------------------------------------------------------------
// Reduce j-split partials: out = relu((sum acc) / (sum deg))
// ---------------------------------------------------------------------------
__global__ void finalize_kernel(const float* __restrict__ accp,
                                const float* __restrict__ degp,
                                float* __restrict__ out) {
    int idx = blockIdx.x * 256 + threadIdx.x;   // 0 .. NN*DIN-1
    int i = idx >> 7;
    float a = accp[idx] + accp[idx + NN * DIN] +
              accp[idx + 2 * NN * DIN] + accp[idx + 3 * NN * DIN];
    float d = degp[i] + degp[i + NN] + degp[i + 2 * NN] + degp[i + 3 * NN];
    float v = a / d;
    out[idx] = v > 0.f ? v : 0.f;
}

extern "C" void kernel_launch(void* const* d_in, const int* in_sizes, int n_in,
                              void* d_out, int out_size) {
    const float* x     = (const float*)d_in[0];
    const float* W0    = (const float*)d_in[2];
    const float* b0    = (const float*)d_in[3];
    const float* W1    = (const float*)d_in[4];
    const float* b1    = (const float*)d_in[5];
    const float* W2    = (const float*)d_in[6];
    const float* b2    = (const float*)d_in[7];
    const float* temp  = (const float*)d_in[8];
    const float* theta = (const float*)d_in[9];

    float* out = (float*)d_out;                 // [NN, DIN] first
    float* adj_out = out + (size_t)NN * DIN;    // then [NN*NN] adjacency

    float *outx, *emb, *sq, *xl, *degp, *accp;
    cudaGetSymbolAddress((void**)&outx, g_outx);
    cudaGetSymbolAddress((void**)&emb,  g_emb);
    cudaGetSymbolAddress((void**)&sq,   g_sq);
    cudaGetSymbolAddress((void**)&xl,   g_xl);
    cudaGetSymbolAddress((void**)&degp, g_degp);
    cudaGetSymbolAddress((void**)&accp, g_accp);

    // out_x = relu(x @ W0 + b0)            [2048, 256]
    gemm_bias_kernel<true><<<dim3(HH / 64, NN / 64), 256>>>(x, W0, b0, outx, NN, HH, DIN);
    // emb = relu(out_x @ W1 + b1)          [2048, 64]
    gemm_bias_kernel<true><<<dim3(DE / 64, NN / 64), 256>>>(outx, W1, b1, emb, NN, DE, HH);
    // x_last = x @ W2 + b2                 [2048, 128]
    gemm_bias_kernel<false><<<dim3(DIN / 64, NN / 64), 256>>>(x, W2, b2, xl, NN, DIN, DIN);
    // sq[i] = ||emb_i||^2
    sq_kernel<<<NN / 8, 256>>>(emb, sq);
    // fused adjacency + deg + partial A@x_last
    adj_kernel<<<dim3(NN / BMR, JSPLIT), 256>>>(emb, sq, xl, temp, theta,
                                                adj_out, degp, accp);
    // out = relu((A @ x_last) / deg)
    finalize_kernel<<<(NN * DIN) / 256, 256>>>(accp, degp, out);
}

// round 4
// speedup vs baseline: 1.2640x; 1.2640x over previous
#include <cuda_runtime.h>

#define NN 2048
#define DIN 128
#define HH 256
#define DE 64
#define JSPLIT 16
#define TILES 4              // (NN/BJ)/JSPLIT
#define BMR 64
#define BJ 32
#define EPAD 68              // 68 ≡ 4 (mod 32): conflict-free LDS.128 per-lane rows
#define SPAD 36              // 36 ≡ 4 (mod 32): same property
#define ADJ_SMEM_FLOATS (BMR*EPAD + BJ*DE + BJ*DIN + BMR*SPAD + BJ + 8*BMR)

typedef unsigned long long u64;

__device__ float g_outx[NN * HH];
__device__ float g_emb[NN * DE];
__device__ float g_sq[NN];
__device__ float g_xl[NN * DIN];
__device__ float g_degp[JSPLIT * NN];
__device__ float g_accp[(size_t)JSPLIT * NN * DIN];

__device__ __forceinline__ float fast_rcp(float x) {
    float r = __uint_as_float(0x7EF311C3u - __float_as_uint(x));
    r = r * (2.0f - x * r);
    r = r * (2.0f - x * r);
    return r;
}

__device__ __forceinline__ u64 pack2(float lo, float hi) {
    u64 r; asm("mov.b64 %0, {%1, %2};" : "=l"(r) : "f"(lo), "f"(hi)); return r;
}
__device__ __forceinline__ void fma2(u64& d, u64 a, u64 b) {
    asm("fma.rn.f32x2 %0, %1, %2, %0;" : "+l"(d) : "l"(a), "l"(b));
}
__device__ __forceinline__ float2 unpack2(u64 v) {
    float2 r; asm("mov.b64 {%0, %1}, %2;" : "=f"(r.x), "=f"(r.y) : "l"(v)); return r;
}

// ---------------------------------------------------------------------------
// Tiled GEMM with bias + optional ReLU + optional fused row-sq (requires the
// block to cover all N columns, i.e. gridDim.x == 1 for the SQ instantiation).
// ---------------------------------------------------------------------------
template <bool RELU, bool SQ>
__global__ void gemm_bias_kernel(const float* __restrict__ A,
                                 const float* __restrict__ B,
                                 const float* __restrict__ bias,
                                 float* __restrict__ C,
                                 float* __restrict__ sqout,
                                 int M, int N, int K) {
    __shared__ float As[16][64];
    __shared__ float Bs[16][65];
    int tid = threadIdx.x;
    int tx = tid & 15, ty = tid >> 4;
    int mbase = blockIdx.y * 64;
    int nbase = blockIdx.x * 64;

    float acc[4][4];
#pragma unroll
    for (int i = 0; i < 4; i++)
#pragma unroll
        for (int j = 0; j < 4; j++) acc[i][j] = 0.f;

    for (int k0 = 0; k0 < K; k0 += 16) {
        {
            int m = tid >> 2;
            int k = (tid & 3) << 2;
            float4 av = *reinterpret_cast<const float4*>(
                A + (size_t)(mbase + m) * K + k0 + k);
            As[k + 0][m] = av.x; As[k + 1][m] = av.y;
            As[k + 2][m] = av.z; As[k + 3][m] = av.w;
        }
#pragma unroll
        for (int r = 0; r < 4; r++) {
            int idx = tid + r * 256;
            int kk = idx >> 6, n = idx & 63;
            Bs[kk][n] = B[(size_t)(k0 + kk) * N + nbase + n];
        }
        __syncthreads();
#pragma unroll
        for (int kk = 0; kk < 16; kk++) {
            float a[4], b[4];
#pragma unroll
            for (int i = 0; i < 4; i++) a[i] = As[kk][ty * 4 + i];
#pragma unroll
            for (int j = 0; j < 4; j++) b[j] = Bs[kk][tx * 4 + j];
#pragma unroll
            for (int i = 0; i < 4; i++)
#pragma unroll
                for (int j = 0; j < 4; j++) acc[i][j] += a[i] * b[j];
        }
        __syncthreads();
    }

    float rowsq[4] = {0.f, 0.f, 0.f, 0.f};
#pragma unroll
    for (int i = 0; i < 4; i++) {
        int row = mbase + ty * 4 + i;
#pragma unroll
        for (int j = 0; j < 4; j++) {
            int col = nbase + tx * 4 + j;
            float v = acc[i][j] + bias[col];
            if (RELU) v = v > 0.f ? v : 0.f;
            C[(size_t)row * N + col] = v;
            if (SQ) rowsq[i] += v * v;
        }
    }
    if constexpr (SQ) {
        __shared__ float sqred[64][17];
#pragma unroll
        for (int i = 0; i < 4; i++) sqred[ty * 4 + i][tx] = rowsq[i];
        __syncthreads();
        if (tid < 64) {
            float s = 0.f;
#pragma unroll
            for (int j = 0; j < 16; j++) s += sqred[tid][j];
            sqout[mbase + tid] = s;
        }
    }
}

// ---------------------------------------------------------------------------
// Fused adjacency kernel: block = 64 A-rows x (TILES*32) cols (one j-split).
// 256 threads; thread owns rows (i, i+32) and col-quad wq*4..+3, d-group wq*16.
// All heavy math via packed fp32x2 FMA; all smem traffic vectorized LDS.128.
// ---------------------------------------------------------------------------
__global__ __launch_bounds__(256, 2)
void adj_kernel(const float* __restrict__ emb, const float* __restrict__ sq,
                const float* __restrict__ xl, const float* __restrict__ temp_p,
                const float* __restrict__ theta_p, float* __restrict__ adj_out,
                float* __restrict__ degp, float* __restrict__ accp) {
    extern __shared__ float sm[];
    float* embi   = sm;                      // BMR*EPAD
    float* embj   = embi + BMR * EPAD;       // BJ*DE (broadcast reads, no pad)
    float* xls    = embj + BJ * DE;          // BJ*DIN (broadcast reads)
    float* Ssm    = xls + BJ * DIN;          // BMR*SPAD
    float* sqjs   = Ssm + BMR * SPAD;        // BJ
    float* degred = sqjs + BJ;               // 8*BMR

    const int t = threadIdx.x;
    const int i0 = blockIdx.x * BMR;
    const int j0 = blockIdx.y * (TILES * BJ);
    const float cA = 1.0f + *temp_p;
    const float cB = 5.0f + *theta_p;

    // stage embi (64x64) as float4, padded rows
    for (int idx = t; idx < BMR * (DE / 4); idx += 256) {
        int r = idx >> 4, c = idx & 15;
        *(float4*)&embi[r * EPAD + c * 4] =
            *(const float4*)&emb[(size_t)(i0 + r) * DE + c * 4];
    }

    const int i = t & 31;
    const int wq = t >> 5;
    const float sqi0 = sq[i0 + i];
    const float sqi1 = sq[i0 + i + 32];

    u64 acc0[8], acc1[8];
#pragma unroll
    for (int u = 0; u < 8; u++) { acc0[u] = 0ull; acc1[u] = 0ull; }
    float dega = 0.f, degb = 0.f;

    for (int jt = 0; jt < TILES; ++jt) {
        const int jb = j0 + jt * BJ;
        __syncthreads();   // smem reuse barrier (also covers first-iter embi)

        for (int idx = t; idx < BJ * (DE / 4); idx += 256) {
            int r = idx >> 4, c = idx & 15;
            *(float4*)&embj[r * DE + c * 4] =
                *(const float4*)&emb[(size_t)(jb + r) * DE + c * 4];
        }
        for (int idx = t; idx < BJ * (DIN / 4); idx += 256) {
            int r = idx >> 5, c = idx & 31;
            *(float4*)&xls[r * DIN + c * 4] =
                *(const float4*)&xl[(size_t)(jb + r) * DIN + c * 4];
        }
        if (t < BJ) sqjs[t] = sq[jb + t];
        __syncthreads();

        // ---- dots for rows i, i+32 x cols wq*4+q, packed f32x2 ----
        u64 dd0[4][2], dd1[4][2];
#pragma unroll
        for (int q = 0; q < 4; q++) {
            dd0[q][0] = 0ull; dd0[q][1] = 0ull;
            dd1[q][0] = 0ull; dd1[q][1] = 0ull;
        }
#pragma unroll
        for (int k4 = 0; k4 < DE / 4; ++k4) {
            ulonglong2 a0 = *(const ulonglong2*)&embi[i * EPAD + k4 * 4];
            ulonglong2 a1 = *(const ulonglong2*)&embi[(i + 32) * EPAD + k4 * 4];
#pragma unroll
            for (int q = 0; q < 4; q++) {
                ulonglong2 b = *(const ulonglong2*)&embj[(wq * 4 + q) * DE + k4 * 4];
                fma2(dd0[q][0], a0.x, b.x); fma2(dd0[q][1], a0.y, b.y);
                fma2(dd1[q][0], a1.x, b.x); fma2(dd1[q][1], a1.y, b.y);
            }
        }
        float p0v[4], p1v[4];
#pragma unroll
        for (int q = 0; q < 4; q++) {
            int jj = wq * 4 + q;
            float2 u0 = unpack2(dd0[q][0]), v0 = unpack2(dd0[q][1]);
            float2 u1 = unpack2(dd1[q][0]), v1 = unpack2(dd1[q][1]);
            float d0 = (u0.x + u0.y) + (v0.x + v0.y);
            float d1 = (u1.x + u1.y) + (v1.x + v1.y);
            float z0 = cA * (2.f * d0 - sqi0 - sqjs[jj]) + cB;
            float z1 = cA * (2.f * d1 - sqi1 - sqjs[jj]) + cB;
            float p0 = fast_rcp(1.f + __expf(-z0));
            float p1 = fast_rcp(1.f + __expf(-z1));
            if (i0 + i == jb + jj) p0 += 1.f;
            if (i0 + i + 32 == jb + jj) p1 += 1.f;
            dega += p0; degb += p1;
            p0v[q] = p0; p1v[q] = p1;
        }
        *(float4*)&Ssm[i * SPAD + wq * 4] =
            make_float4(p0v[0], p0v[1], p0v[2], p0v[3]);
        *(float4*)&Ssm[(i + 32) * SPAD + wq * 4] =
            make_float4(p1v[0], p1v[1], p1v[2], p1v[3]);
        __syncthreads();

        // ---- coalesced adjacency write (128B segments per 8 lanes) ----
        for (int idx = t; idx < BMR * (BJ / 4); idx += 256) {
            int r = idx >> 3, c = idx & 7;
            *(float4*)&adj_out[(size_t)(i0 + r) * NN + jb + c * 4] =
                *(const float4*)&Ssm[r * SPAD + c * 4];
        }

        // ---- acc += S @ x_last, 2 rows share every xls load ----
#pragma unroll
        for (int jjq = 0; jjq < 8; ++jjq) {
            float4 s0 = *(const float4*)&Ssm[i * SPAD + jjq * 4];
            float4 s1 = *(const float4*)&Ssm[(i + 32) * SPAD + jjq * 4];
            float s0a[4] = {s0.x, s0.y, s0.z, s0.w};
            float s1a[4] = {s1.x, s1.y, s1.z, s1.w};
#pragma unroll
            for (int q = 0; q < 4; q++) {
                int jj = jjq * 4 + q;
                u64 sd0 = pack2(s0a[q], s0a[q]);
                u64 sd1 = pack2(s1a[q], s1a[q]);
#pragma unroll
                for (int v = 0; v < 4; ++v) {
                    ulonglong2 xv =
                        *(const ulonglong2*)&xls[jj * DIN + wq * 16 + v * 4];
                    fma2(acc0[v * 2], sd0, xv.x); fma2(acc0[v * 2 + 1], sd0, xv.y);
                    fma2(acc1[v * 2], sd1, xv.x); fma2(acc1[v * 2 + 1], sd1, xv.y);
                }
            }
        }
    }

    // ---- deterministic deg reduction ----
    degred[wq * BMR + i] = dega;
    degred[wq * BMR + 32 + i] = degb;
    __syncthreads();
    if (t < BMR) {
        float d = 0.f;
#pragma unroll
        for (int w = 0; w < 8; w++) d += degred[w * BMR + t];
        degp[blockIdx.y * NN + i0 + t] = d;
    }

    // ---- write partial acc ----
    float* a0p = &accp[((size_t)blockIdx.y * NN + i0 + i) * DIN + wq * 16];
    float* a1p = &accp[((size_t)blockIdx.y * NN + i0 + i + 32) * DIN + wq * 16];
#pragma unroll
    for (int u = 0; u < 8; ++u) {
        float2 w0 = unpack2(acc0[u]);
        float2 w1 = unpack2(acc1[u]);
        *(float2*)&a0p[u * 2] = w0;
        *(float2*)&a1p[u * 2] = w1;
    }
}

// ---------------------------------------------------------------------------
// Reduce j-split partials: out = relu((sum acc) / (sum deg))
// ---------------------------------------------------------------------------
__global__ void finalize_kernel(const float* __restrict__ accp,
                                const float* __restrict__ degp,
                                float* __restrict__ out) {
    __shared__ float ds[2];
    int base = blockIdx.x * 256;
    int t = threadIdx.x;
    if (t < 2) {
        int row = (base >> 7) + t;
        float d = 0.f;
#pragma unroll
        for (int k = 0; k < JSPLIT; k++) d += degp[k * NN + row];
        ds[t] = d;
    }
    __syncthreads();
    int idx = base + t;
    float a = 0.f;
#pragma unroll
    for (int k = 0; k < JSPLIT; k++) a += accp[(size_t)k * NN * DIN + idx];
    float v = a / ds[t >> 7];
    out[idx] = v > 0.f ? v : 0.f;
}

extern "C" void kernel_launch(void* const* d_in, const int* in_sizes, int n_in,
                              void* d_out, int out_size) {
    const float* x     = (const float*)d_in[0];
    const float* W0    = (const float*)d_in[2];
    const float* b0    = (const float*)d_in[3];
    const float* W1    = (const float*)d_in[4];
    const float* b1    = (const float*)d_in[5];
    const float* W2    = (const float*)d_in[6];
    const float* b2    = (const float*)d_in[7];
    const float* temp  = (const float*)d_in[8];
    const float* theta = (const float*)d_in[9];

    float* out = (float*)d_out;                 // [NN, DIN] first
    float* adj_out = out + (size_t)NN * DIN;    // then [NN*NN] adjacency

    float *outx, *emb, *sq, *xl, *degp, *accp;
    cudaGetSymbolAddress((void**)&outx, g_outx);
    cudaGetSymbolAddress((void**)&emb,  g_emb);
    cudaGetSymbolAddress((void**)&sq,   g_sq);
    cudaGetSymbolAddress((void**)&xl,   g_xl);
    cudaGetSymbolAddress((void**)&degp, g_degp);
    cudaGetSymbolAddress((void**)&accp, g_accp);

    cudaFuncSetAttribute((const void*)adj_kernel,
                         cudaFuncAttributeMaxDynamicSharedMemorySize,
                         ADJ_SMEM_FLOATS * 4);

    // out_x = relu(x @ W0 + b0)            [2048, 256]
    gemm_bias_kernel<true, false><<<dim3(HH / 64, NN / 64), 256>>>(
        x, W0, b0, outx, nullptr, NN, HH, DIN);
    // emb = relu(out_x @ W1 + b1) + fused sq   [2048, 64]
    gemm_bias_kernel<true, true><<<dim3(DE / 64, NN / 64), 256>>>(
        outx, W1, b1, emb, sq, NN, DE, HH);
    // x_last = x @ W2 + b2                 [2048, 128]
    gemm_bias_kernel<false, false><<<dim3(DIN / 64, NN / 64), 256>>>(
        x, W2, b2, xl, nullptr, NN, DIN, DIN);
    // fused adjacency + deg + partial A@x_last
    adj_kernel<<<dim3(NN / BMR, JSPLIT), 256, ADJ_SMEM_FLOATS * 4>>>(
        emb, sq, xl, temp, theta, adj_out, degp, accp);
    // out = relu((A @ x_last) / deg)
    finalize_kernel<<<(NN * DIN) / 256, 256>>>(accp, degp, out);
}

// round 5
// speedup vs baseline: 1.5629x; 1.2364x over previous
#include <cuda_runtime.h>

#define NN 2048
#define DIN 128
#define HH 256
#define DE 64
#define JSPLIT 8
#define TILES 8              // (NN/BJ)/JSPLIT
#define BMR 64
#define BJ 32
#define EPAD 68              // 68 ≡ 4 (mod 32): conflict-free LDS.128 per-lane rows
#define SPAD 36              // 36 ≡ 4 (mod 32): same property
#define ADJ_SMEM_FLOATS (BMR*EPAD + BJ*DE + BJ*DIN + BMR*SPAD + BJ + 8*BMR)

typedef unsigned long long u64;

__device__ float g_outx[NN * HH];
__device__ float g_emb[NN * DE];
__device__ float g_sq[NN];
__device__ float g_xl[NN * DIN];
__device__ float g_degp[JSPLIT * NN];
__device__ float g_accp[(size_t)JSPLIT * NN * DIN];

__device__ __forceinline__ float fast_rcp(float x) {
    float r = __uint_as_float(0x7EF311C3u - __float_as_uint(x));
    r = r * (2.0f - x * r);
    r = r * (2.0f - x * r);
    return r;
}

__device__ __forceinline__ u64 pack2(float lo, float hi) {
    u64 r; asm("mov.b64 %0, {%1, %2};" : "=l"(r) : "f"(lo), "f"(hi)); return r;
}
__device__ __forceinline__ void fma2(u64& d, u64 a, u64 b) {
    asm("fma.rn.f32x2 %0, %1, %2, %0;" : "+l"(d) : "l"(a), "l"(b));
}
__device__ __forceinline__ float2 unpack2(u64 v) {
    float2 r; asm("mov.b64 {%0, %1}, %2;" : "=f"(r.x), "=f"(r.y) : "l"(v)); return r;
}

// ---------------------------------------------------------------------------
// Merged prologue GEMM on x: blocks 0..3 -> out_x = relu(x@W0+b0) [2048,256]
//                            blocks 4..5 -> x_last = x@W2+b2      [2048,128]
// BM=BN=64, BK=16, 256 threads, 4x4 per thread. K = DIN = 128.
// ---------------------------------------------------------------------------
__global__ void gemm01_kernel(const float* __restrict__ A,
                              const float* __restrict__ W0,
                              const float* __restrict__ b0,
                              float* __restrict__ outx,
                              const float* __restrict__ W2,
                              const float* __restrict__ b2,
                              float* __restrict__ xl) {
    __shared__ float As[16][64];
    __shared__ float Bs[16][65];
    const bool second = blockIdx.x >= 4;
    const float* B = second ? W2 : W0;
    const float* bias = second ? b2 : b0;
    float* C = second ? xl : outx;
    const int N = second ? DIN : HH;
    const int nbase = (second ? (blockIdx.x - 4) : blockIdx.x) * 64;

    int tid = threadIdx.x;
    int tx = tid & 15, ty = tid >> 4;
    int mbase = blockIdx.y * 64;

    float acc[4][4];
#pragma unroll
    for (int i = 0; i < 4; i++)
#pragma unroll
        for (int j = 0; j < 4; j++) acc[i][j] = 0.f;

#pragma unroll
    for (int k0 = 0; k0 < DIN; k0 += 16) {
        {
            int m = tid >> 2;
            int k = (tid & 3) << 2;
            float4 av = *reinterpret_cast<const float4*>(
                A + (size_t)(mbase + m) * DIN + k0 + k);
            As[k + 0][m] = av.x; As[k + 1][m] = av.y;
            As[k + 2][m] = av.z; As[k + 3][m] = av.w;
        }
#pragma unroll
        for (int r = 0; r < 4; r++) {
            int idx = tid + r * 256;
            int kk = idx >> 6, n = idx & 63;
            Bs[kk][n] = B[(size_t)(k0 + kk) * N + nbase + n];
        }
        __syncthreads();
#pragma unroll
        for (int kk = 0; kk < 16; kk++) {
            float a[4], b[4];
#pragma unroll
            for (int i = 0; i < 4; i++) a[i] = As[kk][ty * 4 + i];
#pragma unroll
            for (int j = 0; j < 4; j++) b[j] = Bs[kk][tx * 4 + j];
#pragma unroll
            for (int i = 0; i < 4; i++)
#pragma unroll
                for (int j = 0; j < 4; j++) acc[i][j] += a[i] * b[j];
        }
        __syncthreads();
    }
#pragma unroll
    for (int i = 0; i < 4; i++) {
        int row = mbase + ty * 4 + i;
#pragma unroll
        for (int j = 0; j < 4; j++) {
            int col = nbase + tx * 4 + j;
            float v = acc[i][j] + bias[col];
            if (!second) v = v > 0.f ? v : 0.f;
            C[(size_t)row * N + col] = v;
        }
    }
}

// ---------------------------------------------------------------------------
// emb GEMM: emb = relu(out_x @ W1 + b1) [2048,64] with fused row-sq.
// Block covers all 64 cols (grid.x == 1).
// ---------------------------------------------------------------------------
__global__ void gemm_emb_kernel(const float* __restrict__ A,
                                const float* __restrict__ B,
                                const float* __restrict__ bias,
                                float* __restrict__ C,
                                float* __restrict__ sqout) {
    __shared__ float As[16][64];
    __shared__ float Bs[16][65];
    const int N = DE, K = HH;
    int tid = threadIdx.x;
    int tx = tid & 15, ty = tid >> 4;
    int mbase = blockIdx.y * 64;

    float acc[4][4];
#pragma unroll
    for (int i = 0; i < 4; i++)
#pragma unroll
        for (int j = 0; j < 4; j++) acc[i][j] = 0.f;

#pragma unroll 4
    for (int k0 = 0; k0 < K; k0 += 16) {
        {
            int m = tid >> 2;
            int k = (tid & 3) << 2;
            float4 av = *reinterpret_cast<const float4*>(
                A + (size_t)(mbase + m) * K + k0 + k);
            As[k + 0][m] = av.x; As[k + 1][m] = av.y;
            As[k + 2][m] = av.z; As[k + 3][m] = av.w;
        }
        // only 64 cols exist; first 4*256 ids cover 16x64
#pragma unroll
        for (int r = 0; r < 4; r++) {
            int idx = tid + r * 256;
            int kk = idx >> 6, n = idx & 63;
            Bs[kk][n] = B[(size_t)(k0 + kk) * N + n];
        }
        __syncthreads();
#pragma unroll
        for (int kk = 0; kk < 16; kk++) {
            float a[4], b[4];
#pragma unroll
            for (int i = 0; i < 4; i++) a[i] = As[kk][ty * 4 + i];
#pragma unroll
            for (int j = 0; j < 4; j++) b[j] = Bs[kk][tx * 4 + j];
#pragma unroll
            for (int i = 0; i < 4; i++)
#pragma unroll
                for (int j = 0; j < 4; j++) acc[i][j] += a[i] * b[j];
        }
        __syncthreads();
    }

    float rowsq[4] = {0.f, 0.f, 0.f, 0.f};
#pragma unroll
    for (int i = 0; i < 4; i++) {
        int row = mbase + ty * 4 + i;
#pragma unroll
        for (int j = 0; j < 4; j++) {
            int col = tx * 4 + j;
            float v = acc[i][j] + bias[col];
            v = v > 0.f ? v : 0.f;
            C[(size_t)row * N + col] = v;
            rowsq[i] += v * v;
        }
    }
    __shared__ float sqred[64][17];
#pragma unroll
    for (int i = 0; i < 4; i++) sqred[ty * 4 + i][tx] = rowsq[i];
    __syncthreads();
    if (tid < 64) {
        float s = 0.f;
#pragma unroll
        for (int j = 0; j < 16; j++) s += sqred[tid][j];
        sqout[mbase + tid] = s;
    }
}

// ---------------------------------------------------------------------------
// Fused adjacency kernel: block = 64 A-rows x (TILES*32) cols (one j-split).
// Dot phase: thread owns rows (i, i+32), col-quad wq*4..+3  (lane i, warp wq)
// Acc phase: warp wq owns rows wq*8..+7, lane owns d-cols i*4..+3 (coalesced)
// ---------------------------------------------------------------------------
__global__ __launch_bounds__(256, 2)
void adj_kernel(const float* __restrict__ emb, const float* __restrict__ sq,
                const float* __restrict__ xl, const float* __restrict__ temp_p,
                const float* __restrict__ theta_p, float* __restrict__ adj_out,
                float* __restrict__ degp, float* __restrict__ accp) {
    extern __shared__ float sm[];
    float* embi   = sm;                      // BMR*EPAD
    float* embj   = embi + BMR * EPAD;       // BJ*DE (broadcast reads, no pad)
    float* xls    = embj + BJ * DE;          // BJ*DIN (coalesced float4 reads)
    float* Ssm    = xls + BJ * DIN;          // BMR*SPAD
    float* sqjs   = Ssm + BMR * SPAD;        // BJ
    float* degred = sqjs + BJ;               // 8*BMR

    const int t = threadIdx.x;
    const int i0 = blockIdx.x * BMR;
    const int j0 = blockIdx.y * (TILES * BJ);
    const float cA = 1.0f + *temp_p;
    const float cB = 5.0f + *theta_p;

    // stage embi (64x64) as float4, padded rows
    for (int idx = t; idx < BMR * (DE / 4); idx += 256) {
        int r = idx >> 4, c = idx & 15;
        *(float4*)&embi[r * EPAD + c * 4] =
            *(const float4*)&emb[(size_t)(i0 + r) * DE + c * 4];
    }

    const int i = t & 31;
    const int wq = t >> 5;
    const float sqi0 = sq[i0 + i];
    const float sqi1 = sq[i0 + i + 32];

    u64 acc[16];           // acc phase: 8 rows x 4 d-cols (f32x2 pairs)
#pragma unroll
    for (int u = 0; u < 16; u++) acc[u] = 0ull;
    float dega = 0.f, degb = 0.f;

    for (int jt = 0; jt < TILES; ++jt) {
        const int jb = j0 + jt * BJ;
        __syncthreads();   // smem reuse barrier (also covers first-iter embi)

        for (int idx = t; idx < BJ * (DE / 4); idx += 256) {
            int r = idx >> 4, c = idx & 15;
            *(float4*)&embj[r * DE + c * 4] =
                *(const float4*)&emb[(size_t)(jb + r) * DE + c * 4];
        }
        for (int idx = t; idx < BJ * (DIN / 4); idx += 256) {
            int r = idx >> 5, c = idx & 31;
            *(float4*)&xls[r * DIN + c * 4] =
                *(const float4*)&xl[(size_t)(jb + r) * DIN + c * 4];
        }
        if (t < BJ) sqjs[t] = sq[jb + t];
        __syncthreads();

        // ---- dots for rows i, i+32 x cols wq*4+q, packed f32x2 ----
        u64 dd0[4][2], dd1[4][2];
#pragma unroll
        for (int q = 0; q < 4; q++) {
            dd0[q][0] = 0ull; dd0[q][1] = 0ull;
            dd1[q][0] = 0ull; dd1[q][1] = 0ull;
        }
#pragma unroll
        for (int k4 = 0; k4 < DE / 4; ++k4) {
            ulonglong2 a0 = *(const ulonglong2*)&embi[i * EPAD + k4 * 4];
            ulonglong2 a1 = *(const ulonglong2*)&embi[(i + 32) * EPAD + k4 * 4];
#pragma unroll
            for (int q = 0; q < 4; q++) {
                ulonglong2 b = *(const ulonglong2*)&embj[(wq * 4 + q) * DE + k4 * 4];
                fma2(dd0[q][0], a0.x, b.x); fma2(dd0[q][1], a0.y, b.y);
                fma2(dd1[q][0], a1.x, b.x); fma2(dd1[q][1], a1.y, b.y);
            }
        }
        float p0v[4], p1v[4];
#pragma unroll
        for (int q = 0; q < 4; q++) {
            int jj = wq * 4 + q;
            float2 u0 = unpack2(dd0[q][0]), v0 = unpack2(dd0[q][1]);
            float2 u1 = unpack2(dd1[q][0]), v1 = unpack2(dd1[q][1]);
            float d0 = (u0.x + u0.y) + (v0.x + v0.y);
            float d1 = (u1.x + u1.y) + (v1.x + v1.y);
            float z0 = cA * (2.f * d0 - sqi0 - sqjs[jj]) + cB;
            float z1 = cA * (2.f * d1 - sqi1 - sqjs[jj]) + cB;
            float p0 = fast_rcp(1.f + __expf(-z0));
            float p1 = fast_rcp(1.f + __expf(-z1));
            if (i0 + i == jb + jj) p0 += 1.f;
            if (i0 + i + 32 == jb + jj) p1 += 1.f;
            dega += p0; degb += p1;
            p0v[q] = p0; p1v[q] = p1;
        }
        *(float4*)&Ssm[i * SPAD + wq * 4] =
            make_float4(p0v[0], p0v[1], p0v[2], p0v[3]);
        *(float4*)&Ssm[(i + 32) * SPAD + wq * 4] =
            make_float4(p1v[0], p1v[1], p1v[2], p1v[3]);
        __syncthreads();

        // ---- coalesced adjacency write (128B segments per 8 lanes) ----
        for (int idx = t; idx < BMR * (BJ / 4); idx += 256) {
            int r = idx >> 3, c = idx & 7;
            *(float4*)&adj_out[(size_t)(i0 + r) * NN + jb + c * 4] =
                *(const float4*)&Ssm[r * SPAD + c * 4];
        }

        // ---- acc phase: warp wq -> rows wq*8..+7, lane -> d-cols i*4..+3 ----
#pragma unroll
        for (int jjq = 0; jjq < 8; ++jjq) {
            float4 sv[8];
#pragma unroll
            for (int r = 0; r < 8; r++)
                sv[r] = *(const float4*)&Ssm[(wq * 8 + r) * SPAD + jjq * 4];
#pragma unroll
            for (int q = 0; q < 4; q++) {
                ulonglong2 xv =
                    *(const ulonglong2*)&xls[(jjq * 4 + q) * DIN + i * 4];
#pragma unroll
                for (int r = 0; r < 8; r++) {
                    float s = (q == 0) ? sv[r].x : (q == 1) ? sv[r].y
                            : (q == 2) ? sv[r].z : sv[r].w;
                    u64 s2 = pack2(s, s);
                    fma2(acc[r * 2], s2, xv.x);
                    fma2(acc[r * 2 + 1], s2, xv.y);
                }
            }
        }
    }

    // ---- deterministic deg reduction ----
    degred[wq * BMR + i] = dega;
    degred[wq * BMR + 32 + i] = degb;
    __syncthreads();
    if (t < BMR) {
        float d = 0.f;
#pragma unroll
        for (int w = 0; w < 8; w++) d += degred[w * BMR + t];
        degp[blockIdx.y * NN + i0 + t] = d;
    }

    // ---- write partial acc: row wq*8+r, cols i*4..+3 (coalesced) ----
#pragma unroll
    for (int r = 0; r < 8; ++r) {
        float2 w0 = unpack2(acc[r * 2]);
        float2 w1 = unpack2(acc[r * 2 + 1]);
        *(float4*)&accp[((size_t)blockIdx.y * NN + i0 + wq * 8 + r) * DIN + i * 4] =
            make_float4(w0.x, w0.y, w1.x, w1.y);
    }
}

// ---------------------------------------------------------------------------
// Reduce j-split partials: out = relu((sum acc) / (sum deg)).  float4 lanes.
// Block handles 1024 floats = 8 rows.
// ---------------------------------------------------------------------------
__global__ void finalize_kernel(const float* __restrict__ accp,
                                const float* __restrict__ degp,
                                float* __restrict__ out) {
    __shared__ float ds[8];
    const int t = threadIdx.x;
    const int base4 = blockIdx.x * 256;     // float4 index base
    if (t < 8) {
        int row = blockIdx.x * 8 + t;
        float d = 0.f;
#pragma unroll
        for (int k = 0; k < JSPLIT; k++) d += degp[k * NN + row];
        ds[t] = d;
    }
    __syncthreads();
    const int idx4 = base4 + t;
    const float4* ap = (const float4*)accp;
    float4 a = ap[idx4];
#pragma unroll
    for (int k = 1; k < JSPLIT; k++) {
        float4 b = ap[(size_t)k * (NN * DIN / 4) + idx4];
        a.x += b.x; a.y += b.y; a.z += b.z; a.w += b.w;
    }
    float dinv = 1.0f / ds[t >> 5];
    float4 v;
    v.x = a.x * dinv; v.y = a.y * dinv; v.z = a.z * dinv; v.w = a.w * dinv;
    v.x = v.x > 0.f ? v.x : 0.f;  v.y = v.y > 0.f ? v.y : 0.f;
    v.z = v.z > 0.f ? v.z : 0.f;  v.w = v.w > 0.f ? v.w : 0.f;
    ((float4*)out)[idx4] = v;
}

extern "C" void kernel_launch(void* const* d_in, const int* in_sizes, int n_in,
                              void* d_out, int out_size) {
    const float* x     = (const float*)d_in[0];
    const float* W0    = (const float*)d_in[2];
    const float* b0    = (const float*)d_in[3];
    const float* W1    = (const float*)d_in[4];
    const float* b1    = (const float*)d_in[5];
    const float* W2    = (const float*)d_in[6];
    const float* b2    = (const float*)d_in[7];
    const float* temp  = (const float*)d_in[8];
    const float* theta = (const float*)d_in[9];

    float* out = (float*)d_out;                 // [NN, DIN] first
    float* adj_out = out + (size_t)NN * DIN;    // then [NN*NN] adjacency

    float *outx, *emb, *sq, *xl, *degp, *accp;
    cudaGetSymbolAddress((void**)&outx, g_outx);
    cudaGetSymbolAddress((void**)&emb,  g_emb);
    cudaGetSymbolAddress((void**)&sq,   g_sq);
    cudaGetSymbolAddress((void**)&xl,   g_xl);
    cudaGetSymbolAddress((void**)&degp, g_degp);
    cudaGetSymbolAddress((void**)&accp, g_accp);

    cudaFuncSetAttribute((const void*)adj_kernel,
                         cudaFuncAttributeMaxDynamicSharedMemorySize,
                         ADJ_SMEM_FLOATS * 4);

    // out_x = relu(x@W0+b0) and x_last = x@W2+b2 in one launch
    gemm01_kernel<<<dim3(6, NN / 64), 256>>>(x, W0, b0, outx, W2, b2, xl);
    // emb = relu(out_x @ W1 + b1) + fused sq   [2048, 64]
    gemm_emb_kernel<<<dim3(1, NN / 64), 256>>>(outx, W1, b1, emb, sq);
    // fused adjacency + deg + partial A@x_last
    adj_kernel<<<dim3(NN / BMR, JSPLIT), 256, ADJ_SMEM_FLOATS * 4>>>(
        emb, sq, xl, temp, theta, adj_out, degp, accp);
    // out = relu((A @ x_last) / deg)
    finalize_kernel<<<(NN * DIN / 4) / 256, 256>>>(accp, degp, out);
}

// round 7
// speedup vs baseline: 1.9964x; 1.2774x over previous
#include <cuda_runtime.h>
#include <cuda_bf16.h>
#include <cstdint>

#define NN 2048
#define DIN 128
#define HH 256
#define DE 64
#define JSPLIT 8
#define JTILE 64
#define TILES 4              // (NN / JSPLIT) / JTILE
#define IBLK 128

typedef unsigned long long u64;
typedef unsigned int u32;

__device__ float g_outx[NN * HH];
__device__ float g_emb[NN * DE];
__device__ float g_sq[NN];
__device__ float g_xl[NN * DIN];
__device__ float g_degp[JSPLIT * NN];
__device__ float g_accp[(size_t)JSPLIT * NN * DIN];

// ---- smem layout (bytes). pitches: 144B (72 bf16) and 272B (136 bf16):
// pitch mod 128 == 16 -> ldmatrix 8-row reads land on disjoint bank quads.
#define P1B 144u
#define P2B 272u
#define OF_EI_H 0u                    // 128 x P1B
#define OF_EI_L (OF_EI_H + 128u*P1B)
#define OF_EJ_H (OF_EI_L + 128u*P1B) // 64 x P1B
#define OF_EJ_L (OF_EJ_H + 64u*P1B)
#define OF_XT_H (OF_EJ_L + 64u*P1B)  // 64 x P2B
#define OF_XT_L (OF_XT_H + 64u*P2B)
#define OF_S_H  (OF_XT_L + 64u*P2B)  // 128 x P1B
#define OF_S_L  (OF_S_H + 128u*P1B)
#define OF_SQJ  (OF_S_L + 128u*P1B)  // 64 floats
#define ADJ_SMEM_BYTES (OF_SQJ + 256u)

__device__ __forceinline__ u32 smem_u32(const void* p) {
    u32 a;
    asm("{ .reg .u64 t; cvta.to.shared.u64 t, %1; cvt.u32.u64 %0, t; }"
        : "=r"(a) : "l"(p));
    return a;
}
__device__ __forceinline__ void ldsm4(u32* r, u32 a) {
    asm volatile("ldmatrix.sync.aligned.m8n8.x4.shared.b16 {%0,%1,%2,%3}, [%4];"
        : "=r"(r[0]), "=r"(r[1]), "=r"(r[2]), "=r"(r[3]) : "r"(a));
}
__device__ __forceinline__ void ldsm4t(u32* r, u32 a) {
    asm volatile("ldmatrix.sync.aligned.m8n8.x4.trans.shared.b16 {%0,%1,%2,%3}, [%4];"
        : "=r"(r[0]), "=r"(r[1]), "=r"(r[2]), "=r"(r[3]) : "r"(a));
}
__device__ __forceinline__ void mma_bf16(float* c, const u32* a, u32 b0, u32 b1) {
    asm volatile(
        "mma.sync.aligned.m16n8k16.row.col.f32.bf16.bf16.f32 "
        "{%0,%1,%2,%3}, {%4,%5,%6,%7}, {%8,%9}, {%0,%1,%2,%3};"
        : "+f"(c[0]), "+f"(c[1]), "+f"(c[2]), "+f"(c[3])
        : "r"(a[0]), "r"(a[1]), "r"(a[2]), "r"(a[3]), "r"(b0), "r"(b1));
}
__device__ __forceinline__ float fast_rcp(float x) {
    float r = __uint_as_float(0x7EF311C3u - __float_as_uint(x));
    r = r * (2.0f - x * r);
    r = r * (2.0f - x * r);
    return r;
}
// split v into bf16 hi/lo pairs and store packed u32s to the h/l planes
__device__ __forceinline__ void split_store(float2 v, char* smp, u32 off, u32 ldelta) {
    __nv_bfloat16 h0 = __float2bfloat16(v.x);
    __nv_bfloat16 h1 = __float2bfloat16(v.y);
    float l0 = v.x - __bfloat162float(h0);
    float l1 = v.y - __bfloat162float(h1);
    __nv_bfloat162 hp; hp.x = h0; hp.y = h1;
    __nv_bfloat162 lp; lp.x = __float2bfloat16(l0); lp.y = __float2bfloat16(l1);
    *(__nv_bfloat162*)(smp + off) = hp;
    *(__nv_bfloat162*)(smp + off + ldelta) = lp;
}

// ---------------------------------------------------------------------------
// Merged prologue GEMM on x: blocks 0..3 -> out_x = relu(x@W0+b0) [2048,256]
//                            blocks 4..5 -> x_last = x@W2+b2      [2048,128]
// ---------------------------------------------------------------------------
__global__ void gemm01_kernel(const float* __restrict__ A,
                              const float* __restrict__ W0,
                              const float* __restrict__ b0,
                              float* __restrict__ outx,
                              const float* __restrict__ W2,
                              const float* __restrict__ b2,
                              float* __restrict__ xl) {
    __shared__ float As[16][64];
    __shared__ float Bs[16][65];
    const bool second = blockIdx.x >= 4;
    const float* B = second ? W2 : W0;
    const float* bias = second ? b2 : b0;
    float* C = second ? xl : outx;
    const int N = second ? DIN : HH;
    const int nbase = (second ? (blockIdx.x - 4) : blockIdx.x) * 64;

    int tid = threadIdx.x;
    int tx = tid & 15, ty = tid >> 4;
    int mbase = blockIdx.y * 64;

    float acc[4][4];
#pragma unroll
    for (int i = 0; i < 4; i++)
#pragma unroll
        for (int j = 0; j < 4; j++) acc[i][j] = 0.f;

#pragma unroll
    for (int k0 = 0; k0 < DIN; k0 += 16) {
        {
            int m = tid >> 2;
            int k = (tid & 3) << 2;
            float4 av = *reinterpret_cast<const float4*>(
                A + (size_t)(mbase + m) * DIN + k0 + k);
            As[k + 0][m] = av.x; As[k + 1][m] = av.y;
            As[k + 2][m] = av.z; As[k + 3][m] = av.w;
        }
#pragma unroll
        for (int r = 0; r < 4; r++) {
            int idx = tid + r * 256;
            int kk = idx >> 6, n = idx & 63;
            Bs[kk][n] = B[(size_t)(k0 + kk) * N + nbase + n];
        }
        __syncthreads();
#pragma unroll
        for (int kk = 0; kk < 16; kk++) {
            float a[4], b[4];
#pragma unroll
            for (int i = 0; i < 4; i++) a[i] = As[kk][ty * 4 + i];
#pragma unroll
            for (int j = 0; j < 4; j++) b[j] = Bs[kk][tx * 4 + j];
#pragma unroll
            for (int i = 0; i < 4; i++)
#pragma unroll
                for (int j = 0; j < 4; j++) acc[i][j] += a[i] * b[j];
        }
        __syncthreads();
    }
#pragma unroll
    for (int i = 0; i < 4; i++) {
        int row = mbase + ty * 4 + i;
#pragma unroll
        for (int j = 0; j < 4; j++) {
            int col = nbase + tx * 4 + j;
            float v = acc[i][j] + bias[col];
            if (!second) v = v > 0.f ? v : 0.f;
            C[(size_t)row * N + col] = v;
        }
    }
}

// ---------------------------------------------------------------------------
// emb GEMM: emb = relu(out_x @ W1 + b1) [2048,64] with fused row-sq.
// ---------------------------------------------------------------------------
__global__ void gemm_emb_kernel(const float* __restrict__ A,
                                const float* __restrict__ B,
                                const float* __restrict__ bias,
                                float* __restrict__ C,
                                float* __restrict__ sqout) {
    __shared__ float As[16][64];
    __shared__ float Bs[16][65];
    const int N = DE, K = HH;
    int tid = threadIdx.x;
    int tx = tid & 15, ty = tid >> 4;
    int mbase = blockIdx.y * 64;

    float acc[4][4];
#pragma unroll
    for (int i = 0; i < 4; i++)
#pragma unroll
        for (int j = 0; j < 4; j++) acc[i][j] = 0.f;

#pragma unroll 4
    for (int k0 = 0; k0 < K; k0 += 16) {
        {
            int m = tid >> 2;
            int k = (tid & 3) << 2;
            float4 av = *reinterpret_cast<const float4*>(
                A + (size_t)(mbase + m) * K + k0 + k);
            As[k + 0][m] = av.x; As[k + 1][m] = av.y;
            As[k + 2][m] = av.z; As[k + 3][m] = av.w;
        }
#pragma unroll
        for (int r = 0; r < 4; r++) {
            int idx = tid + r * 256;
            int kk = idx >> 6, n = idx & 63;
            Bs[kk][n] = B[(size_t)(k0 + kk) * N + n];
        }
        __syncthreads();
#pragma unroll
        for (int kk = 0; kk < 16; kk++) {
            float a[4], b[4];
#pragma unroll
            for (int i = 0; i < 4; i++) a[i] = As[kk][ty * 4 + i];
#pragma unroll
            for (int j = 0; j < 4; j++) b[j] = Bs[kk][tx * 4 + j];
#pragma unroll
            for (int i = 0; i < 4; i++)
#pragma unroll
                for (int j = 0; j < 4; j++) acc[i][j] += a[i] * b[j];
        }
        __syncthreads();
    }

    float rowsq[4] = {0.f, 0.f, 0.f, 0.f};
#pragma unroll
    for (int i = 0; i < 4; i++) {
        int row = mbase + ty * 4 + i;
#pragma unroll
        for (int j = 0; j < 4; j++) {
            int col = tx * 4 + j;
            float v = acc[i][j] + bias[col];
            v = v > 0.f ? v : 0.f;
            C[(size_t)row * N + col] = v;
            rowsq[i] += v * v;
        }
    }
    __shared__ float sqred[64][17];
#pragma unroll
    for (int i = 0; i < 4; i++) sqred[ty * 4 + i][tx] = rowsq[i];
    __syncthreads();
    if (tid < 64) {
        float s = 0.f;
#pragma unroll
        for (int j = 0; j < 16; j++) s += sqred[tid][j];
        sqout[mbase + tid] = s;
    }
}

// ---------------------------------------------------------------------------
// Warp-MMA fused adjacency kernel (bf16-split, 3-MMA compensation).
// CTA = 128 i-rows x one j-split (4 tiles of 64 j). 256 threads (8 warps),
// warp wm owns output rows wm*16..+15.
// ---------------------------------------------------------------------------
__global__ __launch_bounds__(256, 1)
void adj_mma_kernel(const float* __restrict__ emb, const float* __restrict__ sq,
                    const float* __restrict__ xl, const float* __restrict__ temp_p,
                    const float* __restrict__ theta_p, float* __restrict__ adj_out,
                    float* __restrict__ degp, float* __restrict__ accp) {
    extern __shared__ char sm[];
    const u32 sb = smem_u32(sm);
    float* sqj = (float*)(sm + OF_SQJ);

    const int t = threadIdx.x;
    const int wm = t >> 5;
    const int lane = t & 31;
    const int i0 = blockIdx.x * IBLK;
    const int jsp = blockIdx.y;
    const int jbase = jsp * (TILES * JTILE);
    const float cA = 1.0f + *temp_p;
    const float cB = 5.0f + *theta_p;

    // ---- stage embi split (128 x 64) ----
    const float2* emb2 = (const float2*)emb;
    for (int idx = t; idx < IBLK * 32; idx += 256) {
        int row = idx >> 5, cp = idx & 31;
        float2 v = emb2[(size_t)(i0 + row) * 32 + cp];
        split_store(v, sm + OF_EI_H, row * P1B + cp * 4, OF_EI_L - OF_EI_H);
    }

    const int ra = wm * 16 + (lane >> 2);
    const int rb = ra + 8;
    const float sra = sq[i0 + ra];
    const float srb = sq[i0 + rb];

    float acc2[16][4];
#pragma unroll
    for (int n = 0; n < 16; n++)
#pragma unroll
        for (int q = 0; q < 4; q++) acc2[n][q] = 0.f;
    float dega = 0.f, degb = 0.f;

    const float2* xl2 = (const float2*)xl;

    for (int tt = 0; tt < TILES; ++tt) {
        const int jb = jbase + tt * JTILE;
        __syncthreads();   // protect smem reuse from prior phase-2 reads

        for (int idx = t; idx < JTILE * 32; idx += 256) {
            int row = idx >> 5, cp = idx & 31;
            float2 v = emb2[(size_t)(jb + row) * 32 + cp];
            split_store(v, sm + OF_EJ_H, row * P1B + cp * 4, OF_EJ_L - OF_EJ_H);
        }
        for (int idx = t; idx < JTILE * 64; idx += 256) {
            int j = idx >> 6, dp = idx & 63;
            float2 v = xl2[(size_t)(jb + j) * 64 + dp];
            split_store(v, sm + OF_XT_H, j * P2B + dp * 4, OF_XT_L - OF_XT_H);
        }
        if (t < JTILE) sqj[t] = sq[jb + t];
        __syncthreads();

        // ---- phase 1: dot = embi @ embj^T ----
        float acc1[8][4];
#pragma unroll
        for (int n = 0; n < 8; n++)
#pragma unroll
            for (int q = 0; q < 4; q++) acc1[n][q] = 0.f;

        u32 ah[4][4], al[4][4];
        const u32 abase = sb + OF_EI_H + (wm * 16 + (lane & 15)) * P1B + (lane >> 4) * 16;
#pragma unroll
        for (int ks = 0; ks < 4; ks++) {
            ldsm4(ah[ks], abase + ks * 32);
            ldsm4(al[ks], abase + (OF_EI_L - OF_EI_H) + ks * 32);
        }
        const u32 bjbase = sb + OF_EJ_H + ((lane & 7) + (lane >> 4) * 8) * P1B
                           + ((lane >> 3) & 1) * 16;
#pragma unroll
        for (int np = 0; np < 4; np++) {
#pragma unroll
            for (int ks = 0; ks < 4; ks++) {
                u32 bh[4], bl[4];
                u32 ba = bjbase + np * 16 * P1B + ks * 32;
                ldsm4(bh, ba);
                ldsm4(bl, ba + (OF_EJ_L - OF_EJ_H));
                mma_bf16(acc1[np * 2],     ah[ks], bh[0], bh[1]);
                mma_bf16(acc1[np * 2],     ah[ks], bl[0], bl[1]);
                mma_bf16(acc1[np * 2],     al[ks], bh[0], bh[1]);
                mma_bf16(acc1[np * 2 + 1], ah[ks], bh[2], bh[3]);
                mma_bf16(acc1[np * 2 + 1], ah[ks], bl[2], bl[3]);
                mma_bf16(acc1[np * 2 + 1], al[ks], bh[2], bh[3]);
            }
        }

        // ---- epilogue: sigmoid + eye, adj STG, deg, S split -> smem ----
#pragma unroll
        for (int nt = 0; nt < 8; nt++) {
            int jc = nt * 8 + 2 * (lane & 3);
            float sj0 = sqj[jc], sj1 = sqj[jc + 1];
            float z00 = cA * (2.f * acc1[nt][0] - sra - sj0) + cB;
            float z01 = cA * (2.f * acc1[nt][1] - sra - sj1) + cB;
            float z10 = cA * (2.f * acc1[nt][2] - srb - sj0) + cB;
            float z11 = cA * (2.f * acc1[nt][3] - srb - sj1) + cB;
            float p00 = fast_rcp(1.f + __expf(-z00));
            float p01 = fast_rcp(1.f + __expf(-z01));
            float p10 = fast_rcp(1.f + __expf(-z10));
            float p11 = fast_rcp(1.f + __expf(-z11));
            if (i0 + ra == jb + jc)     p00 += 1.f;
            if (i0 + ra == jb + jc + 1) p01 += 1.f;
            if (i0 + rb == jb + jc)     p10 += 1.f;
            if (i0 + rb == jb + jc + 1) p11 += 1.f;
            dega += p00 + p01;
            degb += p10 + p11;
            *(float2*)&adj_out[(size_t)(i0 + ra) * NN + jb + jc] = make_float2(p00, p01);
            *(float2*)&adj_out[(size_t)(i0 + rb) * NN + jb + jc] = make_float2(p10, p11);
            split_store(make_float2(p00, p01), sm + OF_S_H,
                        ra * P1B + jc * 2, OF_S_L - OF_S_H);
            split_store(make_float2(p10, p11), sm + OF_S_H,
                        rb * P1B + jc * 2, OF_S_L - OF_S_H);
        }
        __syncthreads();   // S + xls visible to all warps

        // ---- phase 2: acc2 += S @ xls^T (B via ldmatrix.trans) ----
        const u32 sbase = sb + OF_S_H + (wm * 16 + (lane & 15)) * P1B + (lane >> 4) * 16;
        const u32 btbase = sb + OF_XT_H
                           + ((lane & 7) + ((lane >> 3) & 1) * 8) * P2B
                           + (lane >> 4) * 16;
#pragma unroll
        for (int ks = 0; ks < 4; ks++) {
            u32 sh[4], sl[4];
            ldsm4(sh, sbase + ks * 32);
            ldsm4(sl, sbase + (OF_S_L - OF_S_H) + ks * 32);
#pragma unroll
            for (int ndp = 0; ndp < 8; ndp++) {
                u32 bh[4], bl[4];
                u32 ba = btbase + ks * 16 * P2B + ndp * 32;
                ldsm4t(bh, ba);
                ldsm4t(bl, ba + (OF_XT_L - OF_XT_H));
                mma_bf16(acc2[ndp * 2],     sh, bh[0], bh[1]);
                mma_bf16(acc2[ndp * 2],     sh, bl[0], bl[1]);
                mma_bf16(acc2[ndp * 2],     sl, bh[0], bh[1]);
                mma_bf16(acc2[ndp * 2 + 1], sh, bh[2], bh[3]);
                mma_bf16(acc2[ndp * 2 + 1], sh, bl[2], bl[3]);
                mma_bf16(acc2[ndp * 2 + 1], sl, bh[2], bh[3]);
            }
        }
    }

    // ---- deg: reduce across the 4 lanes sharing each row ----
    dega += __shfl_xor_sync(0xffffffffu, dega, 1);
    dega += __shfl_xor_sync(0xffffffffu, dega, 2);
    degb += __shfl_xor_sync(0xffffffffu, degb, 1);
    degb += __shfl_xor_sync(0xffffffffu, degb, 2);
    if ((lane & 3) == 0) {
        degp[jsp * NN + i0 + ra] = dega;
        degp[jsp * NN + i0 + rb] = degb;
    }

    // ---- write acc2 partials ----
    float* ap = accp + ((size_t)jsp * NN + i0) * DIN;
#pragma unroll
    for (int nt = 0; nt < 16; nt++) {
        int dc = nt * 8 + 2 * (lane & 3);
        *(float2*)&ap[(size_t)ra * DIN + dc] = make_float2(acc2[nt][0], acc2[nt][1]);
        *(float2*)&ap[(size_t)rb * DIN + dc] = make_float2(acc2[nt][2], acc2[nt][3]);
    }
}

// ---------------------------------------------------------------------------
// Reduce j-split partials: out = relu((sum acc) / (sum deg)).  float4 lanes.
// ---------------------------------------------------------------------------
__global__ void finalize_kernel(const float* __restrict__ accp,
                                const float* __restrict__ degp,
                                float* __restrict__ out) {
    __shared__ float ds[8];
    const int t = threadIdx.x;
    const int base4 = blockIdx.x * 256;
    if (t < 8) {
        int row = blockIdx.x * 8 + t;
        float d = 0.f;
#pragma unroll
        for (int k = 0; k < JSPLIT; k++) d += degp[k * NN + row];
        ds[t] = d;
    }
    __syncthreads();
    const int idx4 = base4 + t;
    const float4* apv = (const float4*)accp;
    float4 a = apv[idx4];
#pragma unroll
    for (int k = 1; k < JSPLIT; k++) {
        float4 b = apv[(size_t)k * (NN * DIN / 4) + idx4];
        a.x += b.x; a.y += b.y; a.z += b.z; a.w += b.w;
    }
    float dinv = 1.0f / ds[t >> 5];
    float4 v;
    v.x = a.x * dinv; v.y = a.y * dinv; v.z = a.z * dinv; v.w = a.w * dinv;
    v.x = v.x > 0.f ? v.x : 0.f;  v.y = v.y > 0.f ? v.y : 0.f;
    v.z = v.z > 0.f ? v.z : 0.f;  v.w = v.w > 0.f ? v.w : 0.f;
    ((float4*)out)[idx4] = v;
}

extern "C" void kernel_launch(void* const* d_in, const int* in_sizes, int n_in,
                              void* d_out, int out_size) {
    const float* x     = (const float*)d_in[0];
    const float* W0    = (const float*)d_in[2];
    const float* b0    = (const float*)d_in[3];
    const float* W1    = (const float*)d_in[4];
    const float* b1    = (const float*)d_in[5];
    const float* W2    = (const float*)d_in[6];
    const float* b2    = (const float*)d_in[7];
    const float* temp  = (const float*)d_in[8];
    const float* theta = (const float*)d_in[9];

    float* out = (float*)d_out;                 // [NN, DIN] first
    float* adj_out = out + (size_t)NN * DIN;    // then [NN*NN] adjacency

    float *outx, *emb, *sq, *xl, *degp, *accp;
    cudaGetSymbolAddress((void**)&outx, g_outx);
    cudaGetSymbolAddress((void**)&emb,  g_emb);
    cudaGetSymbolAddress((void**)&sq,   g_sq);
    cudaGetSymbolAddress((void**)&xl,   g_xl);
    cudaGetSymbolAddress((void**)&degp, g_degp);
    cudaGetSymbolAddress((void**)&accp, g_accp);

    cudaFuncSetAttribute((const void*)adj_mma_kernel,
                         cudaFuncAttributeMaxDynamicSharedMemorySize,
                         ADJ_SMEM_BYTES);

    // out_x = relu(x@W0+b0) and x_last = x@W2+b2 in one launch
    gemm01_kernel<<<dim3(6, NN / 64), 256>>>(x, W0, b0, outx, W2, b2, xl);
    // emb = relu(out_x @ W1 + b1) + fused sq
    gemm_emb_kernel<<<dim3(1, NN / 64), 256>>>(outx, W1, b1, emb, sq);
    // warp-MMA fused adjacency + deg + partial A@x_last
    adj_mma_kernel<<<dim3(NN / IBLK, JSPLIT), 256, ADJ_SMEM_BYTES>>>(
        emb, sq, xl, temp, theta, adj_out, degp, accp);
    // out = relu((A @ x_last) / deg)
    finalize_kernel<<<(NN * DIN / 4) / 256, 256>>>(accp, degp, out);
}

// round 9
// speedup vs baseline: 2.3389x; 1.1716x over previous
#include <cuda_runtime.h>
#include <cuda_bf16.h>
#include <cstdint>

#define NN 2048
#define DIN 128
#define HH 256
#define DE 64
#define JSPLIT 8
#define JTILE 64
#define TILES 4              // (NN / JSPLIT) / JTILE
#define IBLK 64

typedef unsigned long long u64;
typedef unsigned int u32;

__device__ float g_outx[NN * HH];
__device__ float g_sq[NN];
__device__ __align__(16) __nv_bfloat16 g_embh[NN * DE];
__device__ __align__(16) __nv_bfloat16 g_embl[NN * DE];
__device__ __align__(16) __nv_bfloat16 g_xlh[NN * DIN];
__device__ __align__(16) __nv_bfloat16 g_xll[NN * DIN];
__device__ float g_degp[JSPLIT * NN];
__device__ float g_accp[(size_t)JSPLIT * NN * DIN];

// ---- smem layout (bytes). pitches mod 128B == 16B -> ldmatrix conflict-free.
#define P1B 144u
#define P2B 272u
#define OF_EI_H 0u                    // 64 x P1B
#define OF_EI_L 9216u
#define OF_EJ_H 18432u                // 64 x P1B
#define OF_EJ_L 27648u
#define OF_XT_H 36864u                // 64 x P2B
#define OF_XT_L 54272u
#define OF_S_H  71680u                // 64 x P1B
#define OF_S_L  80896u
#define OF_SQJ  90112u                // 64 floats
#define OF_DEG  90368u                // 2 x 64 floats
#define ADJ_SMEM_BYTES 90880u

__device__ __forceinline__ u32 smem_u32(const void* p) {
    u32 a;
    asm("{ .reg .u64 t; cvta.to.shared.u64 t, %1; cvt.u32.u64 %0, t; }"
        : "=r"(a) : "l"(p));
    return a;
}
__device__ __forceinline__ void ldsm4(u32* r, u32 a) {
    asm volatile("ldmatrix.sync.aligned.m8n8.x4.shared.b16 {%0,%1,%2,%3}, [%4];"
        : "=r"(r[0]), "=r"(r[1]), "=r"(r[2]), "=r"(r[3]) : "r"(a));
}
__device__ __forceinline__ void ldsm4t(u32* r, u32 a) {
    asm volatile("ldmatrix.sync.aligned.m8n8.x4.trans.shared.b16 {%0,%1,%2,%3}, [%4];"
        : "=r"(r[0]), "=r"(r[1]), "=r"(r[2]), "=r"(r[3]) : "r"(a));
}
__device__ __forceinline__ void mma_bf16(float* c, const u32* a, u32 b0, u32 b1) {
    asm volatile(
        "mma.sync.aligned.m16n8k16.row.col.f32.bf16.bf16.f32 "
        "{%0,%1,%2,%3}, {%4,%5,%6,%7}, {%8,%9}, {%0,%1,%2,%3};"
        : "+f"(c[0]), "+f"(c[1]), "+f"(c[2]), "+f"(c[3])
        : "r"(a[0]), "r"(a[1]), "r"(a[2]), "r"(a[3]), "r"(b0), "r"(b1));
}
__device__ __forceinline__ float fast_rcp(float x) {
    float r = __uint_as_float(0x7EF311C3u - __float_as_uint(x));
    r = r * (2.0f - x * r);
    r = r * (2.0f - x * r);
    return r;
}
// split v pair into bf16 hi/lo and store packed u32s to the h/l smem planes
__device__ __forceinline__ void split_store(float2 v, char* smp, u32 off, u32 ldelta) {
    __nv_bfloat16 h0 = __float2bfloat16(v.x);
    __nv_bfloat16 h1 = __float2bfloat16(v.y);
    float l0 = v.x - __bfloat162float(h0);
    float l1 = v.y - __bfloat162float(h1);
    __nv_bfloat162 hp; hp.x = h0; hp.y = h1;
    __nv_bfloat162 lp; lp.x = __float2bfloat16(l0); lp.y = __float2bfloat16(l1);
    *(__nv_bfloat162*)(smp + off) = hp;
    *(__nv_bfloat162*)(smp + off + ldelta) = lp;
}
// split v pair into bf16 hi/lo, store packed to two global bf16 planes
__device__ __forceinline__ void split_store_g(float v0, float v1,
                                              __nv_bfloat16* gh, __nv_bfloat16* gl) {
    __nv_bfloat16 h0 = __float2bfloat16(v0);
    __nv_bfloat16 h1 = __float2bfloat16(v1);
    float l0 = v0 - __bfloat162float(h0);
    float l1 = v1 - __bfloat162float(h1);
    __nv_bfloat162 hp; hp.x = h0; hp.y = h1;
    __nv_bfloat162 lp; lp.x = __float2bfloat16(l0); lp.y = __float2bfloat16(l1);
    *(__nv_bfloat162*)gh = hp;
    *(__nv_bfloat162*)gl = lp;
}

// ---------------------------------------------------------------------------
// Merged prologue GEMM on x:
//   blocks 0..3 -> out_x = relu(x@W0+b0) fp32 [2048,256]
//   blocks 4..5 -> x_last = x@W2+b2 -> bf16 hi/lo planes xlh/xll [2048,128]
// ---------------------------------------------------------------------------
__global__ void gemm01_kernel(const float* __restrict__ A,
                              const float* __restrict__ W0,
                              const float* __restrict__ b0,
                              float* __restrict__ outx,
                              const float* __restrict__ W2,
                              const float* __restrict__ b2,
                              __nv_bfloat16* __restrict__ xlh,
                              __nv_bfloat16* __restrict__ xll) {
    __shared__ float As[16][64];
    __shared__ float Bs[16][65];
    const bool second = blockIdx.x >= 4;
    const float* B = second ? W2 : W0;
    const float* bias = second ? b2 : b0;
    const int N = second ? DIN : HH;
    const int nbase = (second ? (blockIdx.x - 4) : blockIdx.x) * 64;

    int tid = threadIdx.x;
    int tx = tid & 15, ty = tid >> 4;
    int mbase = blockIdx.y * 64;

    float acc[4][4];
#pragma unroll
    for (int i = 0; i < 4; i++)
#pragma unroll
        for (int j = 0; j < 4; j++) acc[i][j] = 0.f;

#pragma unroll
    for (int k0 = 0; k0 < DIN; k0 += 16) {
        {
            int m = tid >> 2;
            int k = (tid & 3) << 2;
            float4 av = *reinterpret_cast<const float4*>(
                A + (size_t)(mbase + m) * DIN + k0 + k);
            As[k + 0][m] = av.x; As[k + 1][m] = av.y;
            As[k + 2][m] = av.z; As[k + 3][m] = av.w;
        }
#pragma unroll
        for (int r = 0; r < 4; r++) {
            int idx = tid + r * 256;
            int kk = idx >> 6, n = idx & 63;
            Bs[kk][n] = B[(size_t)(k0 + kk) * N + nbase + n];
        }
        __syncthreads();
#pragma unroll
        for (int kk = 0; kk < 16; kk++) {
            float a[4], b[4];
#pragma unroll
            for (int i = 0; i < 4; i++) a[i] = As[kk][ty * 4 + i];
#pragma unroll
            for (int j = 0; j < 4; j++) b[j] = Bs[kk][tx * 4 + j];
#pragma unroll
            for (int i = 0; i < 4; i++)
#pragma unroll
                for (int j = 0; j < 4; j++) acc[i][j] += a[i] * b[j];
        }
        __syncthreads();
    }
#pragma unroll
    for (int i = 0; i < 4; i++) {
        int row = mbase + ty * 4 + i;
        if (!second) {
#pragma unroll
            for (int j = 0; j < 4; j++) {
                int col = nbase + tx * 4 + j;
                float v = acc[i][j] + bias[col];
                outx[(size_t)row * HH + col] = v > 0.f ? v : 0.f;
            }
        } else {
            int col = nbase + tx * 4;
            float v[4];
#pragma unroll
            for (int j = 0; j < 4; j++) v[j] = acc[i][j] + bias[col + j];
            split_store_g(v[0], v[1], &xlh[(size_t)row * DIN + col],
                          &xll[(size_t)row * DIN + col]);
            split_store_g(v[2], v[3], &xlh[(size_t)row * DIN + col + 2],
                          &xll[(size_t)row * DIN + col + 2]);
        }
    }
}

// ---------------------------------------------------------------------------
// emb GEMM: emb = relu(out_x @ W1 + b1) -> bf16 hi/lo planes + fused row-sq.
// ---------------------------------------------------------------------------
__global__ void gemm_emb_kernel(const float* __restrict__ A,
                                const float* __restrict__ B,
                                const float* __restrict__ bias,
                                __nv_bfloat16* __restrict__ embh,
                                __nv_bfloat16* __restrict__ embl,
                                float* __restrict__ sqout) {
    __shared__ float As[16][64];
    __shared__ float Bs[16][65];
    const int N = DE, K = HH;
    int tid = threadIdx.x;
    int tx = tid & 15, ty = tid >> 4;
    int mbase = blockIdx.y * 64;

    float acc[4][4];
#pragma unroll
    for (int i = 0; i < 4; i++)
#pragma unroll
        for (int j = 0; j < 4; j++) acc[i][j] = 0.f;

#pragma unroll 4
    for (int k0 = 0; k0 < K; k0 += 16) {
        {
            int m = tid >> 2;
            int k = (tid & 3) << 2;
            float4 av = *reinterpret_cast<const float4*>(
                A + (size_t)(mbase + m) * K + k0 + k);
            As[k + 0][m] = av.x; As[k + 1][m] = av.y;
            As[k + 2][m] = av.z; As[k + 3][m] = av.w;
        }
#pragma unroll
        for (int r = 0; r < 4; r++) {
            int idx = tid + r * 256;
            int kk = idx >> 6, n = idx & 63;
            Bs[kk][n] = B[(size_t)(k0 + kk) * N + n];
        }
        __syncthreads();
#pragma unroll
        for (int kk = 0; kk < 16; kk++) {
            float a[4], b[4];
#pragma unroll
            for (int i = 0; i < 4; i++) a[i] = As[kk][ty * 4 + i];
#pragma unroll
            for (int j = 0; j < 4; j++) b[j] = Bs[kk][tx * 4 + j];
#pragma unroll
            for (int i = 0; i < 4; i++)
#pragma unroll
                for (int j = 0; j < 4; j++) acc[i][j] += a[i] * b[j];
        }
        __syncthreads();
    }

    float rowsq[4] = {0.f, 0.f, 0.f, 0.f};
#pragma unroll
    for (int i = 0; i < 4; i++) {
        int row = mbase + ty * 4 + i;
        int col = tx * 4;
        float v[4];
#pragma unroll
        for (int j = 0; j < 4; j++) {
            float u = acc[i][j] + bias[col + j];
            u = u > 0.f ? u : 0.f;
            v[j] = u;
            rowsq[i] += u * u;
        }
        split_store_g(v[0], v[1], &embh[(size_t)row * DE + col],
                      &embl[(size_t)row * DE + col]);
        split_store_g(v[2], v[3], &embh[(size_t)row * DE + col + 2],
                      &embl[(size_t)row * DE + col + 2]);
    }
    __shared__ float sqred[64][17];
#pragma unroll
    for (int i = 0; i < 4; i++) sqred[ty * 4 + i][tx] = rowsq[i];
    __syncthreads();
    if (tid < 64) {
        float s = 0.f;
#pragma unroll
        for (int j = 0; j < 16; j++) s += sqred[tid][j];
        sqout[mbase + tid] = s;
    }
}

// ---------------------------------------------------------------------------
// Warp-MMA fused adjacency kernel (bf16-split, 3-MMA compensation).
// CTA = 64 i-rows x one j-split (4 tiles of 64 j). 256 threads (8 warps):
//   wr = wm&3 -> row group wr*16..+15;  wg = wm>>2 -> j-half (phase1) and
//   d-half (phase2). 2 CTAs/SM (90.9KB smem).
// ---------------------------------------------------------------------------
__global__ __launch_bounds__(256, 2)
void adj_mma_kernel(const __nv_bfloat16* __restrict__ embh,
                    const __nv_bfloat16* __restrict__ embl,
                    const float* __restrict__ sq,
                    const __nv_bfloat16* __restrict__ xlh,
                    const __nv_bfloat16* __restrict__ xll,
                    const float* __restrict__ temp_p,
                    const float* __restrict__ theta_p,
                    float* __restrict__ adj_out,
                    float* __restrict__ degp, float* __restrict__ accp) {
    extern __shared__ char sm[];
    const u32 sb = smem_u32(sm);
    float* sqjc  = (float*)(sm + OF_SQJ);
    float* degsm = (float*)(sm + OF_DEG);

    const int t = threadIdx.x;
    const int wm = t >> 5;
    const int lane = t & 31;
    const int wg = wm >> 2;
    const int wr = wm & 3;
    const int i0 = blockIdx.x * IBLK;
    const int jsp = blockIdx.y;
    const int jbase = jsp * (TILES * JTILE);
    const float cA = 1.0f + *temp_p;
    const float cB = 5.0f + *theta_p;
    const float c2A = 2.0f * cA;

    // ---- stage EI planes (pure copies, 64 rows x 128B per plane) ----
    {
        const uint4* sH = (const uint4*)embh + (size_t)i0 * 8;
        const uint4* sL = (const uint4*)embl + (size_t)i0 * 8;
        for (int idx = t; idx < 512; idx += 256) {
            int row = idx >> 3, q = idx & 7;
            *(uint4*)(sm + OF_EI_H + row * P1B + q * 16) = sH[row * 8 + q];
            *(uint4*)(sm + OF_EI_L + row * P1B + q * 16) = sL[row * 8 + q];
        }
    }
    __syncthreads();

    // ---- A fragments (tile-invariant, hoisted) ----
    u32 ah[4][4], al[4][4];
    {
        const u32 abase = sb + OF_EI_H + (wr * 16 + (lane & 15)) * P1B + (lane >> 4) * 16;
#pragma unroll
        for (int ks = 0; ks < 4; ks++) {
            ldsm4(ah[ks], abase + ks * 32);
            ldsm4(al[ks], abase + (OF_EI_L - OF_EI_H) + ks * 32);
        }
    }

    const int ra = wr * 16 + (lane >> 2);
    const int rb = ra + 8;
    const float cbi_a = cB - cA * sq[i0 + ra];
    const float cbi_b = cB - cA * sq[i0 + rb];

    float acc2[8][4];
#pragma unroll
    for (int n = 0; n < 8; n++)
#pragma unroll
        for (int q = 0; q < 4; q++) acc2[n][q] = 0.f;
    float dega = 0.f, degb = 0.f;

    for (int tt = 0; tt < TILES; ++tt) {
        const int jb = jbase + tt * JTILE;
        if (tt > 0) __syncthreads();   // prior phase-2 reads of EJ/XT/S done

        // stage EJ planes
        {
            const uint4* sH = (const uint4*)embh + (size_t)jb * 8;
            const uint4* sL = (const uint4*)embl + (size_t)jb * 8;
            for (int idx = t; idx < 512; idx += 256) {
                int row = idx >> 3, q = idx & 7;
                *(uint4*)(sm + OF_EJ_H + row * P1B + q * 16) = sH[row * 8 + q];
                *(uint4*)(sm + OF_EJ_L + row * P1B + q * 16) = sL[row * 8 + q];
            }
        }
        // stage XT planes (64 rows x 256B per plane)
        {
            const uint4* sH = (const uint4*)xlh + (size_t)jb * 16;
            const uint4* sL = (const uint4*)xll + (size_t)jb * 16;
            for (int idx = t; idx < 1024; idx += 256) {
                int row = idx >> 4, q = idx & 15;
                *(uint4*)(sm + OF_XT_H + row * P2B + q * 16) = sH[row * 16 + q];
                *(uint4*)(sm + OF_XT_L + row * P2B + q * 16) = sL[row * 16 + q];
            }
        }
        if (t < JTILE) sqjc[t] = cA * sq[jb + t];
        __syncthreads();

        // ---- phase 1: dot = embi @ embj^T (warp: 16 rows x 32 j) ----
        float acc1[4][4];
#pragma unroll
        for (int n = 0; n < 4; n++)
#pragma unroll
            for (int q = 0; q < 4; q++) acc1[n][q] = 0.f;

        const u32 bjbase = sb + OF_EJ_H
                           + (wg * 32 + (lane & 7) + (lane >> 4) * 8) * P1B
                           + ((lane >> 3) & 1) * 16;
#pragma unroll
        for (int np = 0; np < 2; np++) {
#pragma unroll
            for (int ks = 0; ks < 4; ks++) {
                u32 bh[4], bl[4];
                u32 ba = bjbase + np * 16 * P1B + ks * 32;
                ldsm4(bh, ba);
                ldsm4(bl, ba + (OF_EJ_L - OF_EJ_H));
                mma_bf16(acc1[np * 2],     ah[ks], bh[0], bh[1]);
                mma_bf16(acc1[np * 2],     ah[ks], bl[0], bl[1]);
                mma_bf16(acc1[np * 2],     al[ks], bh[0], bh[1]);
                mma_bf16(acc1[np * 2 + 1], ah[ks], bh[2], bh[3]);
                mma_bf16(acc1[np * 2 + 1], ah[ks], bl[2], bl[3]);
                mma_bf16(acc1[np * 2 + 1], al[ks], bh[2], bh[3]);
            }
        }

        // ---- epilogue: sigmoid + eye, adj STG, deg, S split -> smem ----
#pragma unroll
        for (int nt = 0; nt < 4; nt++) {
            int jc = wg * 32 + nt * 8 + 2 * (lane & 3);
            float sj0 = sqjc[jc], sj1 = sqjc[jc + 1];
            float z00 = fmaf(c2A, acc1[nt][0], cbi_a - sj0);
            float z01 = fmaf(c2A, acc1[nt][1], cbi_a - sj1);
            float z10 = fmaf(c2A, acc1[nt][2], cbi_b - sj0);
            float z11 = fmaf(c2A, acc1[nt][3], cbi_b - sj1);
            float p00 = fast_rcp(1.f + __expf(-z00));
            float p01 = fast_rcp(1.f + __expf(-z01));
            float p10 = fast_rcp(1.f + __expf(-z10));
            float p11 = fast_rcp(1.f + __expf(-z11));
            if (i0 + ra == jb + jc)     p00 += 1.f;
            if (i0 + ra == jb + jc + 1) p01 += 1.f;
            if (i0 + rb == jb + jc)     p10 += 1.f;
            if (i0 + rb == jb + jc + 1) p11 += 1.f;
            dega += p00 + p01;
            degb += p10 + p11;
            *(float2*)&adj_out[(size_t)(i0 + ra) * NN + jb + jc] = make_float2(p00, p01);
            *(float2*)&adj_out[(size_t)(i0 + rb) * NN + jb + jc] = make_float2(p10, p11);
            split_store(make_float2(p00, p01), sm + OF_S_H,
                        ra * P1B + jc * 2, OF_S_L - OF_S_H);
            split_store(make_float2(p10, p11), sm + OF_S_H,
                        rb * P1B + jc * 2, OF_S_L - OF_S_H);
        }
        __syncthreads();   // S visible to all warps

        // ---- phase 2: acc2 += S @ XT^T (warp: 16 rows x 64 d, K=64) ----
        const u32 sbase = sb + OF_S_H + (wr * 16 + (lane & 15)) * P1B + (lane >> 4) * 16;
        const u32 btbase = sb + OF_XT_H
                           + ((lane & 7) + ((lane >> 3) & 1) * 8) * P2B
                           + wg * 128 + (lane >> 4) * 16;
#pragma unroll
        for (int ks = 0; ks < 4; ks++) {
            u32 sh[4], sl[4];
            ldsm4(sh, sbase + ks * 32);
            ldsm4(sl, sbase + (OF_S_L - OF_S_H) + ks * 32);
#pragma unroll
            for (int ndp = 0; ndp < 4; ndp++) {
                u32 bh[4], bl[4];
                u32 ba = btbase + ks * 16 * P2B + ndp * 32;
                ldsm4t(bh, ba);
                ldsm4t(bl, ba + (OF_XT_L - OF_XT_H));
                mma_bf16(acc2[ndp * 2],     sh, bh[0], bh[1]);
                mma_bf16(acc2[ndp * 2],     sh, bl[0], bl[1]);
                mma_bf16(acc2[ndp * 2],     sl, bh[0], bh[1]);
                mma_bf16(acc2[ndp * 2 + 1], sh, bh[2], bh[3]);
                mma_bf16(acc2[ndp * 2 + 1], sh, bl[2], bl[3]);
                mma_bf16(acc2[ndp * 2 + 1], sl, bh[2], bh[3]);
            }
        }
    }

    // ---- deg: lanes (j-quads) then the two j-half warps via smem ----
    dega += __shfl_xor_sync(0xffffffffu, dega, 1);
    dega += __shfl_xor_sync(0xffffffffu, dega, 2);
    degb += __shfl_xor_sync(0xffffffffu, degb, 1);
    degb += __shfl_xor_sync(0xffffffffu, degb, 2);
    if ((lane & 3) == 0) {
        degsm[wg * IBLK + ra] = dega;
        degsm[wg * IBLK + rb] = degb;
    }
    __syncthreads();
    if (t < IBLK)
        degp[jsp * NN + i0 + t] = degsm[t] + degsm[IBLK + t];

    // ---- write acc2 partials (rows ra/rb, d-cols wg*64 + ...) ----
    float* ap = accp + ((size_t)jsp * NN + i0) * DIN;
#pragma unroll
    for (int nt = 0; nt < 8; nt++) {
        int dc = wg * 64 + nt * 8 + 2 * (lane & 3);
        *(float2*)&ap[(size_t)ra * DIN + dc] = make_float2(acc2[nt][0], acc2[nt][1]);
        *(float2*)&ap[(size_t)rb * DIN + dc] = make_float2(acc2[nt][2], acc2[nt][3]);
    }
}

// ---------------------------------------------------------------------------
// Reduce j-split partials: out = relu((sum acc) / (sum deg)).  float4 lanes.
// ---------------------------------------------------------------------------
__global__ void finalize_kernel(const float* __restrict__ accp,
                                const float* __restrict__ degp,
                                float* __restrict__ out) {
    __shared__ float ds[8];
    const int t = threadIdx.x;
    const int base4 = blockIdx.x * 256;
    if (t < 8) {
        int row = blockIdx.x * 8 + t;
        float d = 0.f;
#pragma unroll
        for (int k = 0; k < JSPLIT; k++) d += degp[k * NN + row];
        ds[t] = d;
    }
    __syncthreads();
    const int idx4 = base4 + t;
    const float4* apv = (const float4*)accp;
    float4 a = apv[idx4];
#pragma unroll
    for (int k = 1; k < JSPLIT; k++) {
        float4 b = apv[(size_t)k * (NN * DIN / 4) + idx4];
        a.x += b.x; a.y += b.y; a.z += b.z; a.w += b.w;
    }
    float dinv = 1.0f / ds[t >> 5];
    float4 v;
    v.x = a.x * dinv; v.y = a.y * dinv; v.z = a.z * dinv; v.w = a.w * dinv;
    v.x = v.x > 0.f ? v.x : 0.f;  v.y = v.y > 0.f ? v.y : 0.f;
    v.z = v.z > 0.f ? v.z : 0.f;  v.w = v.w > 0.f ? v.w : 0.f;
    ((float4*)out)[idx4] = v;
}

extern "C" void kernel_launch(void* const* d_in, const int* in_sizes, int n_in,
                              void* d_out, int out_size) {
    const float* x     = (const float*)d_in[0];
    const float* W0    = (const float*)d_in[2];
    const float* b0    = (const float*)d_in[3];
    const float* W1    = (const float*)d_in[4];
    const float* b1    = (const float*)d_in[5];
    const float* W2    = (const float*)d_in[6];
    const float* b2    = (const float*)d_in[7];
    const float* temp  = (const float*)d_in[8];
    const float* theta = (const float*)d_in[9];

    float* out = (float*)d_out;                 // [NN, DIN] first
    float* adj_out = out + (size_t)NN * DIN;    // then [NN*NN] adjacency

    float *outx, *sq, *degp, *accp;
    __nv_bfloat16 *embh, *embl, *xlh, *xll;
    cudaGetSymbolAddress((void**)&outx, g_outx);
    cudaGetSymbolAddress((void**)&sq,   g_sq);
    cudaGetSymbolAddress((void**)&embh, g_embh);
    cudaGetSymbolAddress((void**)&embl, g_embl);
    cudaGetSymbolAddress((void**)&xlh,  g_xlh);
    cudaGetSymbolAddress((void**)&xll,  g_xll);
    cudaGetSymbolAddress((void**)&degp, g_degp);
    cudaGetSymbolAddress((void**)&accp, g_accp);

    cudaFuncSetAttribute((const void*)adj_mma_kernel,
                         cudaFuncAttributeMaxDynamicSharedMemorySize,
                         ADJ_SMEM_BYTES);

    // out_x = relu(x@W0+b0) fp32; x_last = x@W2+b2 -> bf16 hi/lo planes
    gemm01_kernel<<<dim3(6, NN / 64), 256>>>(x, W0, b0, outx, W2, b2, xlh, xll);
    // emb = relu(out_x @ W1 + b1) -> bf16 hi/lo planes + row sq
    gemm_emb_kernel<<<dim3(1, NN / 64), 256>>>(outx, W1, b1, embh, embl, sq);
    // warp-MMA fused adjacency + deg + partial A@x_last
    adj_mma_kernel<<<dim3(NN / IBLK, JSPLIT), 256, ADJ_SMEM_BYTES>>>(
        embh, embl, sq, xlh, xll, temp, theta, adj_out, degp, accp);
    // out = relu((A @ x_last) / deg)
    finalize_kernel<<<(NN * DIN / 4) / 256, 256>>>(accp, degp, out);
}